// round 3
// baseline (speedup 1.0000x reference)
#include <cuda_runtime.h>
#include <math_constants.h>

#define NN   50000
#define NE   800000
#define NET  (NE + NN)          // 850000 edges incl. self loops
#define FIN  128
#define FHID 128
#define FOUT 64
#define NEG  0.2f

// ---------------- scratch (static device globals; no allocation) ----------------
__device__ float g_h1[NN * FHID];     // 25.6 MB
__device__ float g_acc1[NN * FHID];   // 25.6 MB
__device__ float g_h2[NN * FOUT];     // 12.8 MB
__device__ float g_as[NN];
__device__ float g_ad[NN];
__device__ float g_m[NN];
__device__ float g_den[NN];
__device__ float g_e[NET];

// ---------------- GEMM: C[M,NC] = A[M,128] @ B[128,NC], fp32 ----------------
template<int NC>
__global__ void __launch_bounds__(256) gemm_k(const float* __restrict__ A,
                                              const float* __restrict__ B,
                                              float* __restrict__ C, int M) {
    constexpr int K = 128, BM = 64, KC = 32;
    constexpr int COLG = NC / 4;        // groups of 4 cols
    constexpr int ROWT = 256 / COLG;    // threads along rows
    constexpr int RPT  = BM / ROWT;     // rows per thread
    __shared__ float As[BM][KC];
    __shared__ float Bs[KC][NC];

    const int tid  = threadIdx.x;
    const int row0 = blockIdx.x * BM;
    const int tx   = tid % COLG;
    const int ty   = tid / COLG;

    float acc[RPT][4];
#pragma unroll
    for (int i = 0; i < RPT; i++)
#pragma unroll
        for (int j = 0; j < 4; j++) acc[i][j] = 0.f;

    for (int kc = 0; kc < K; kc += KC) {
        // load A tile (BM x KC)
        for (int i = tid; i < BM * KC / 4; i += 256) {
            int r = i / (KC / 4);
            int c = i % (KC / 4);
            int gr = row0 + r;
            float4 v = make_float4(0.f, 0.f, 0.f, 0.f);
            if (gr < M)
                v = ((const float4*)A)[(size_t)gr * (K / 4) + (kc / 4) + c];
            *(float4*)&As[r][c * 4] = v;
        }
        // load B tile (KC x NC)
        for (int i = tid; i < KC * NC / 4; i += 256) {
            int r = i / (NC / 4);
            int c = i % (NC / 4);
            *(float4*)&Bs[r][c * 4] = ((const float4*)B)[(size_t)(kc + r) * (NC / 4) + c];
        }
        __syncthreads();

#pragma unroll
        for (int k = 0; k < KC; k++) {
            float4 b = *(const float4*)&Bs[k][tx * 4];
#pragma unroll
            for (int i = 0; i < RPT; i++) {
                float a = As[ty * RPT + i][k];   // warp-broadcast
                acc[i][0] += a * b.x;
                acc[i][1] += a * b.y;
                acc[i][2] += a * b.z;
                acc[i][3] += a * b.w;
            }
        }
        __syncthreads();
    }

#pragma unroll
    for (int i = 0; i < RPT; i++) {
        int gr = row0 + ty * RPT + i;
        if (gr < M)
            *(float4*)&C[(size_t)gr * NC + tx * 4] =
                make_float4(acc[i][0], acc[i][1], acc[i][2], acc[i][3]);
    }
}

// ---------------- per-node attention logits: as[i]=h[i]·a_src, ad[i]=h[i]·a_dst ----
template<int F>
__global__ void alpha_k(const float* __restrict__ h,
                        const float* __restrict__ a_s,
                        const float* __restrict__ a_d,
                        float* __restrict__ as_out,
                        float* __restrict__ ad_out) {
    int warp = (blockIdx.x * blockDim.x + threadIdx.x) >> 5;
    int lane = threadIdx.x & 31;
    if (warp >= NN) return;
    float ss = 0.f, sd = 0.f;
#pragma unroll
    for (int f = lane; f < F; f += 32) {
        float hv = h[(size_t)warp * F + f];
        ss += hv * a_s[f];
        sd += hv * a_d[f];
    }
#pragma unroll
    for (int o = 16; o; o >>= 1) {
        ss += __shfl_down_sync(0xffffffffu, ss, o);
        sd += __shfl_down_sync(0xffffffffu, sd, o);
    }
    if (lane == 0) { as_out[warp] = ss; ad_out[warp] = sd; }
}

// ---------------- init: m=-inf, den=0, acc=0 ----------------
__global__ void init_k(float* __restrict__ m, float* __restrict__ den,
                       float* __restrict__ acc, int total) {
    int idx = blockIdx.x * blockDim.x + threadIdx.x;
    if (idx < NN) { m[idx] = -CUDART_INF_F; den[idx] = 0.f; }
    if (idx < total) acc[idx] = 0.f;
}

// ---------------- float atomicMax via sign-split int trick ----------------
__device__ __forceinline__ void atomicMaxFloat(float* addr, float val) {
    if (val >= 0.f) atomicMax((int*)addr, __float_as_int(val));
    else            atomicMin((unsigned int*)addr, __float_as_uint(val));
}

// ---------------- edge pass A: e = leaky(as[src]+ad[dst]); segment max ----------
__global__ void edgeA_k(const int* __restrict__ ei,
                        const float* __restrict__ as,
                        const float* __restrict__ ad,
                        float* __restrict__ m,
                        float* __restrict__ e_out) {
    int idx = blockIdx.x * blockDim.x + threadIdx.x;
    if (idx >= NET) return;
    int s, d;
    if (idx < NE) { s = ei[idx]; d = ei[NE + idx]; }
    else          { s = d = idx - NE; }
    float e = as[s] + ad[d];
    e = e > 0.f ? e : NEG * e;
    e_out[idx] = e;
    atomicMaxFloat(&m[d], e);
}

// ---------------- edge pass B: w=exp(e-m[dst]); den[dst]+=w; acc[dst]+=w*h[src] ----
template<int F>
__global__ void edgeB_k(const int* __restrict__ ei,
                        const float* __restrict__ h,
                        const float* __restrict__ e_in,
                        const float* __restrict__ m,
                        float* __restrict__ den,
                        float* __restrict__ acc) {
    constexpr int LPE = F / 4;   // lanes per edge, one float4 each
    long long gt = (long long)blockIdx.x * blockDim.x + threadIdx.x;
    int idx = (int)(gt / LPE);
    int sub = (int)(gt % LPE);
    if (idx >= NET) return;
    int s, d;
    if (idx < NE) { s = ei[idx]; d = ei[NE + idx]; }
    else          { s = d = idx - NE; }
    float w = __expf(e_in[idx] - m[d]);        // redundant per lane; L1/L2 broadcast
    if (sub == 0) atomicAdd(&den[d], w);
    float4 hv = ((const float4*)h)[(size_t)s * LPE + sub];
    float4 v = make_float4(w * hv.x, w * hv.y, w * hv.z, w * hv.w);
    atomicAdd((float4*)&acc[(size_t)d * F + sub * 4], v);   // sm_90+ vector RED
}

// ---------------- node finalize layer 1: acc = relu(acc/den + b) ----------------
__global__ void node1_k(float* __restrict__ acc, const float* __restrict__ den,
                        const float* __restrict__ b) {
    int idx = blockIdx.x * blockDim.x + threadIdx.x;
    if (idx >= NN * FHID) return;
    int node = idx / FHID, f = idx % FHID;
    float v = acc[idx] / den[node] + b[f];
    acc[idx] = v > 0.f ? v : 0.f;
}

// ---------------- node finalize layer 2: out = out/den + b ----------------
__global__ void node2_k(float* __restrict__ out, const float* __restrict__ den,
                        const float* __restrict__ b) {
    int idx = blockIdx.x * blockDim.x + threadIdx.x;
    if (idx >= NN * FOUT) return;
    int node = idx / FOUT, f = idx % FOUT;
    out[idx] = out[idx] / den[node] + b[f];
}

// ---------------- launch ----------------
extern "C" void kernel_launch(void* const* d_in, const int* in_sizes, int n_in,
                              void* d_out, int out_size) {
    const float* x   = (const float*)d_in[0];
    const int*   ei  = (const int*)d_in[1];
    const float* W1  = (const float*)d_in[2];
    const float* a1s = (const float*)d_in[3];
    const float* a1d = (const float*)d_in[4];
    const float* b1  = (const float*)d_in[5];
    const float* W2  = (const float*)d_in[6];
    const float* a2s = (const float*)d_in[7];
    const float* a2d = (const float*)d_in[8];
    const float* b2  = (const float*)d_in[9];
    float* out = (float*)d_out;

    float *h1, *acc1, *h2, *as, *ad, *m, *den, *e;
    cudaGetSymbolAddress((void**)&h1,   g_h1);
    cudaGetSymbolAddress((void**)&acc1, g_acc1);
    cudaGetSymbolAddress((void**)&h2,   g_h2);
    cudaGetSymbolAddress((void**)&as,   g_as);
    cudaGetSymbolAddress((void**)&ad,   g_ad);
    cudaGetSymbolAddress((void**)&m,    g_m);
    cudaGetSymbolAddress((void**)&den,  g_den);
    cudaGetSymbolAddress((void**)&e,    g_e);

    const int T = 256;

    // ---- layer 1 (F=128) ----
    gemm_k<FHID><<<(NN + 63) / 64, T>>>(x, W1, h1, NN);
    alpha_k<FHID><<<(NN * 32 + T - 1) / T, T>>>(h1, a1s, a1d, as, ad);
    init_k<<<(NN * FHID + T - 1) / T, T>>>(m, den, acc1, NN * FHID);
    edgeA_k<<<(NET + T - 1) / T, T>>>(ei, as, ad, m, e);
    edgeB_k<FHID><<<(int)(((long long)NET * 32 + T - 1) / T), T>>>(ei, h1, e, m, den, acc1);
    node1_k<<<(NN * FHID + T - 1) / T, T>>>(acc1, den, b1);

    // ---- layer 2 (F=64) ----
    gemm_k<FOUT><<<(NN + 63) / 64, T>>>(acc1, W2, h2, NN);
    alpha_k<FOUT><<<(NN * 32 + T - 1) / T, T>>>(h2, a2s, a2d, as, ad);
    init_k<<<(NN * FOUT + T - 1) / T, T>>>(m, den, out, NN * FOUT);
    edgeA_k<<<(NET + T - 1) / T, T>>>(ei, as, ad, m, e);
    edgeB_k<FOUT><<<(int)(((long long)NET * 16 + T - 1) / T), T>>>(ei, h2, e, m, den, out);
    node2_k<<<(NN * FOUT + T - 1) / T, T>>>(out, den, b2);
}

// round 4
// speedup vs baseline: 1.8041x; 1.8041x over previous
#include <cuda_runtime.h>
#include <math_constants.h>

#define NN   50000
#define NE   800000
#define NET  (NE + NN)          // 850000 edges incl. self loops
#define FIN  128
#define FHID 128
#define FOUT 64
#define NEG  0.2f

// ---------------- scratch (static device globals; no allocation) ----------------
__device__ float g_h1[NN * FHID];     // 25.6 MB
__device__ float g_acc1[NN * FHID];   // 25.6 MB
__device__ float g_h2[NN * FOUT];     // 12.8 MB
__device__ float g_as[NN];
__device__ float g_ad[NN];
__device__ int   g_cnt[NN];
__device__ int   g_off[NN + 1];
__device__ int   g_cur[NN];
__device__ int   g_srcA[NET];
__device__ int   g_bsum[64];

// ================= f32x2 packed-FMA helpers (sm_100+) =================
__device__ __forceinline__ unsigned long long pack2(float lo, float hi) {
    unsigned long long r;
    asm("mov.b64 %0, {%1, %2};" : "=l"(r) : "f"(lo), "f"(hi));
    return r;
}
__device__ __forceinline__ void ffma2(unsigned long long& d,
                                      unsigned long long a,
                                      unsigned long long b) {
    asm("fma.rn.f32x2 %0, %1, %2, %0;" : "+l"(d) : "l"(a), "l"(b));
}
__device__ __forceinline__ float2 unpack2(unsigned long long v) {
    float2 f;
    asm("mov.b64 {%0, %1}, %2;" : "=f"(f.x), "=f"(f.y) : "l"(v));
    return f;
}

// ================= GEMM: C[M,BN] = A[M,128] @ B[128,BN] (f32x2 FMA) =============
template<int BN>
__global__ void __launch_bounds__(256) gemm2_k(const float* __restrict__ A,
                                               const float* __restrict__ B,
                                               float* __restrict__ C, int M) {
    constexpr int K = 128, BM = 128, BK = 16;
    constexpr int TM = 8, TN = BN / 16;         // 8x8 (BN=128) or 8x4 (BN=64)
    constexpr int NP = TN / 2;                  // f32x2 pairs per row
    __shared__ float As[BK][BM + 4];            // transposed A tile, padded
    __shared__ float Bs[BK][BN];

    const int tid  = threadIdx.x;
    const int tx   = tid & 15;                  // col group (16)
    const int ty   = tid >> 4;                  // row group (16)
    const int row0 = blockIdx.x * BM;

    unsigned long long acc[TM][NP];
#pragma unroll
    for (int m = 0; m < TM; m++)
#pragma unroll
        for (int n = 0; n < NP; n++) acc[m][n] = 0ull;

    const float4* A4 = (const float4*)A;
    const float4* B4 = (const float4*)B;

    for (int kc = 0; kc < K; kc += BK) {
        // load A tile (BM x BK), transposed into As[k][m]
#pragma unroll
        for (int it = 0; it < 2; it++) {
            int i  = tid + it * 256;            // 512 float4 total
            int r  = i >> 2;
            int kg = i & 3;
            float4 v = make_float4(0.f, 0.f, 0.f, 0.f);
            if (row0 + r < M)
                v = A4[(size_t)(row0 + r) * (K / 4) + (kc >> 2) + kg];
            As[kg * 4 + 0][r] = v.x;
            As[kg * 4 + 1][r] = v.y;
            As[kg * 4 + 2][r] = v.z;
            As[kg * 4 + 3][r] = v.w;
        }
        // load B tile (BK x BN)
#pragma unroll
        for (int i = tid; i < BK * BN / 4; i += 256) {
            int r = i / (BN / 4);
            int c = i % (BN / 4);
            *(float4*)&Bs[r][c * 4] = B4[(size_t)(kc + r) * (BN / 4) + c];
        }
        __syncthreads();

#pragma unroll
        for (int k = 0; k < BK; k++) {
            float4 a0 = *(const float4*)&As[k][ty * TM];
            float4 a1 = *(const float4*)&As[k][ty * TM + 4];
            float a[TM] = {a0.x, a0.y, a0.z, a0.w, a1.x, a1.y, a1.z, a1.w};
            unsigned long long bp[NP];
            float4 b0 = *(const float4*)&Bs[k][tx * TN];
            bp[0] = pack2(b0.x, b0.y);
            bp[1] = pack2(b0.z, b0.w);
            if constexpr (TN == 8) {
                float4 b1 = *(const float4*)&Bs[k][tx * TN + 4];
                bp[2] = pack2(b1.x, b1.y);
                bp[3] = pack2(b1.z, b1.w);
            }
#pragma unroll
            for (int m = 0; m < TM; m++) {
                unsigned long long ap = pack2(a[m], a[m]);
#pragma unroll
                for (int n = 0; n < NP; n++) ffma2(acc[m][n], ap, bp[n]);
            }
        }
        __syncthreads();
    }

    // store
#pragma unroll
    for (int m = 0; m < TM; m++) {
        int r = row0 + ty * TM + m;
        if (r < M) {
            float* cp = &C[(size_t)r * BN + tx * TN];
#pragma unroll
            for (int n = 0; n < NP; n += 2) {
                float2 p0 = unpack2(acc[m][n]);
                float2 p1 = unpack2(acc[m][n + 1]);
                *(float4*)(cp + n * 2) = make_float4(p0.x, p0.y, p1.x, p1.y);
            }
        }
    }
}

// ---------------- per-node attention logits ----------------
template<int F>
__global__ void alpha_k(const float* __restrict__ h,
                        const float* __restrict__ a_s,
                        const float* __restrict__ a_d,
                        float* __restrict__ as_out,
                        float* __restrict__ ad_out) {
    int warp = (blockIdx.x * blockDim.x + threadIdx.x) >> 5;
    int lane = threadIdx.x & 31;
    if (warp >= NN) return;
    float ss = 0.f, sd = 0.f;
#pragma unroll
    for (int f = lane; f < F; f += 32) {
        float hv = h[(size_t)warp * F + f];
        ss += hv * a_s[f];
        sd += hv * a_d[f];
    }
#pragma unroll
    for (int o = 16; o; o >>= 1) {
        ss += __shfl_down_sync(0xffffffffu, ss, o);
        sd += __shfl_down_sync(0xffffffffu, sd, o);
    }
    if (lane == 0) { as_out[warp] = ss; ad_out[warp] = sd; }
}

// ================= CSR build (dst-sorted adjacency) =================
__global__ void initcnt_k(int* __restrict__ cnt) {
    int i = blockIdx.x * blockDim.x + threadIdx.x;
    if (i < NN) cnt[i] = 1;            // self loop pre-counted
}

__global__ void hist_k(const int* __restrict__ ei, int* __restrict__ cnt) {
    int idx = blockIdx.x * blockDim.x + threadIdx.x;
    if (idx >= NE) return;
    atomicAdd(&cnt[ei[NE + idx]], 1);
}

__global__ void scan1_k(const int* __restrict__ cnt, int* __restrict__ off,
                        int* __restrict__ bsum) {
    __shared__ int s[1024];
    int tid = threadIdx.x;
    int g = blockIdx.x * 1024 + tid;
    int v = (g < NN) ? cnt[g] : 0;
    s[tid] = v;
    __syncthreads();
#pragma unroll
    for (int o = 1; o < 1024; o <<= 1) {
        int t = (tid >= o) ? s[tid - o] : 0;
        __syncthreads();
        s[tid] += t;
        __syncthreads();
    }
    if (g < NN) off[g + 1] = s[tid];
    if (tid == 1023) bsum[blockIdx.x] = s[1023];
}

__global__ void scan2_k(int* __restrict__ bsum, int nb) {
    if (threadIdx.x == 0) {
        int run = 0;
        for (int i = 0; i < nb; i++) { int v = bsum[i]; bsum[i] = run; run += v; }
    }
}

__global__ void scan3_k(int* __restrict__ off, const int* __restrict__ bsum) {
    int g = blockIdx.x * 1024 + threadIdx.x;
    if (g < NN) off[g + 1] += bsum[blockIdx.x];
    if (g == 0) off[0] = 0;
}

// place self loop at slot off[g], cursor starts after it
__global__ void cur_k(const int* __restrict__ off, int* __restrict__ cur,
                      int* __restrict__ srcA) {
    int g = blockIdx.x * blockDim.x + threadIdx.x;
    if (g >= NN) return;
    int o = off[g];
    cur[g] = o + 1;
    srcA[o] = g;
}

__global__ void scatter_k(const int* __restrict__ ei, int* __restrict__ cur,
                          int* __restrict__ srcA) {
    int idx = blockIdx.x * blockDim.x + threadIdx.x;
    if (idx >= NE) return;
    int s = ei[idx];
    int d = ei[NE + idx];
    int p = atomicAdd(&cur[d], 1);
    srcA[p] = s;
}

// ================= fused gather + softmax + aggregate (one warp / node) ========
template<int F, bool RELU>
__global__ void __launch_bounds__(256) aggregate_k(
    const float* __restrict__ h,
    const float* __restrict__ as,
    const float* __restrict__ ad,
    const int* __restrict__ off,
    const int* __restrict__ srcA,
    const float* __restrict__ bias,
    float* __restrict__ out) {
    int node = (blockIdx.x * blockDim.x + threadIdx.x) >> 5;
    int lane = threadIdx.x & 31;
    if (node >= NN) return;

    int beg = off[node];
    int end = off[node + 1];
    float adn = ad[node];

    constexpr int V = F / 32;               // 4 (F=128) or 2 (F=64)
    float acc[V];
#pragma unroll
    for (int v = 0; v < V; v++) acc[v] = 0.f;
    float den = 0.f;

    const float4* H4 = (const float4*)h;
    const float2* H2 = (const float2*)h;

    for (int base = beg; base < end; base += 32) {
        int k = base + lane;
        int s = 0;
        float w = 0.f;
        if (k < end) {
            s = srcA[k];
            float e = as[s] + adn;
            e = e > 0.f ? e : NEG * e;
            w = __expf(e);                  // no max-shift: softmax invariant, |e|<~15
        }
        den += w;
        int cnt = min(32, end - base);
        int j = 0;
        for (; j + 4 <= cnt; j += 4) {
            int   s0 = __shfl_sync(0xffffffffu, s, j);
            int   s1 = __shfl_sync(0xffffffffu, s, j + 1);
            int   s2 = __shfl_sync(0xffffffffu, s, j + 2);
            int   s3 = __shfl_sync(0xffffffffu, s, j + 3);
            float w0 = __shfl_sync(0xffffffffu, w, j);
            float w1 = __shfl_sync(0xffffffffu, w, j + 1);
            float w2 = __shfl_sync(0xffffffffu, w, j + 2);
            float w3 = __shfl_sync(0xffffffffu, w, j + 3);
            if constexpr (V == 4) {
                float4 h0 = H4[(size_t)s0 * (F / 4) + lane];
                float4 h1 = H4[(size_t)s1 * (F / 4) + lane];
                float4 h2 = H4[(size_t)s2 * (F / 4) + lane];
                float4 h3 = H4[(size_t)s3 * (F / 4) + lane];
                acc[0] += w0 * h0.x + w1 * h1.x + w2 * h2.x + w3 * h3.x;
                acc[1] += w0 * h0.y + w1 * h1.y + w2 * h2.y + w3 * h3.y;
                acc[2] += w0 * h0.z + w1 * h1.z + w2 * h2.z + w3 * h3.z;
                acc[3] += w0 * h0.w + w1 * h1.w + w2 * h2.w + w3 * h3.w;
            } else {
                float2 h0 = H2[(size_t)s0 * (F / 2) + lane];
                float2 h1 = H2[(size_t)s1 * (F / 2) + lane];
                float2 h2 = H2[(size_t)s2 * (F / 2) + lane];
                float2 h3 = H2[(size_t)s3 * (F / 2) + lane];
                acc[0] += w0 * h0.x + w1 * h1.x + w2 * h2.x + w3 * h3.x;
                acc[1] += w0 * h0.y + w1 * h1.y + w2 * h2.y + w3 * h3.y;
            }
        }
        for (; j < cnt; j++) {
            int   sj = __shfl_sync(0xffffffffu, s, j);
            float wj = __shfl_sync(0xffffffffu, w, j);
            if constexpr (V == 4) {
                float4 hv = H4[(size_t)sj * (F / 4) + lane];
                acc[0] += wj * hv.x;
                acc[1] += wj * hv.y;
                acc[2] += wj * hv.z;
                acc[3] += wj * hv.w;
            } else {
                float2 hv = H2[(size_t)sj * (F / 2) + lane];
                acc[0] += wj * hv.x;
                acc[1] += wj * hv.y;
            }
        }
    }

#pragma unroll
    for (int o = 16; o; o >>= 1) den += __shfl_xor_sync(0xffffffffu, den, o);
    float inv = 1.f / den;

    if constexpr (V == 4) {
        float4 b4 = ((const float4*)bias)[lane];
        float4 o4 = make_float4(acc[0] * inv + b4.x, acc[1] * inv + b4.y,
                                acc[2] * inv + b4.z, acc[3] * inv + b4.w);
        if (RELU) {
            o4.x = o4.x > 0.f ? o4.x : 0.f;
            o4.y = o4.y > 0.f ? o4.y : 0.f;
            o4.z = o4.z > 0.f ? o4.z : 0.f;
            o4.w = o4.w > 0.f ? o4.w : 0.f;
        }
        ((float4*)out)[(size_t)node * (F / 4) + lane] = o4;
    } else {
        float2 b2 = ((const float2*)bias)[lane];
        float2 o2 = make_float2(acc[0] * inv + b2.x, acc[1] * inv + b2.y);
        if (RELU) {
            o2.x = o2.x > 0.f ? o2.x : 0.f;
            o2.y = o2.y > 0.f ? o2.y : 0.f;
        }
        ((float2*)out)[(size_t)node * (F / 2) + lane] = o2;
    }
}

// ---------------- launch ----------------
extern "C" void kernel_launch(void* const* d_in, const int* in_sizes, int n_in,
                              void* d_out, int out_size) {
    const float* x   = (const float*)d_in[0];
    const int*   ei  = (const int*)d_in[1];
    const float* W1  = (const float*)d_in[2];
    const float* a1s = (const float*)d_in[3];
    const float* a1d = (const float*)d_in[4];
    const float* b1  = (const float*)d_in[5];
    const float* W2  = (const float*)d_in[6];
    const float* a2s = (const float*)d_in[7];
    const float* a2d = (const float*)d_in[8];
    const float* b2  = (const float*)d_in[9];
    float* out = (float*)d_out;

    float *h1, *acc1, *h2, *as, *ad;
    int *cnt, *off, *cur, *srcA, *bsum;
    cudaGetSymbolAddress((void**)&h1,   g_h1);
    cudaGetSymbolAddress((void**)&acc1, g_acc1);
    cudaGetSymbolAddress((void**)&h2,   g_h2);
    cudaGetSymbolAddress((void**)&as,   g_as);
    cudaGetSymbolAddress((void**)&ad,   g_ad);
    cudaGetSymbolAddress((void**)&cnt,  g_cnt);
    cudaGetSymbolAddress((void**)&off,  g_off);
    cudaGetSymbolAddress((void**)&cur,  g_cur);
    cudaGetSymbolAddress((void**)&srcA, g_srcA);
    cudaGetSymbolAddress((void**)&bsum, g_bsum);

    const int T = 256;
    const int NB = (NN + 1023) / 1024;   // 49

    // ---- CSR build (shared by both layers) ----
    initcnt_k<<<(NN + T - 1) / T, T>>>(cnt);
    hist_k<<<(NE + T - 1) / T, T>>>(ei, cnt);
    scan1_k<<<NB, 1024>>>(cnt, off, bsum);
    scan2_k<<<1, 32>>>(bsum, NB);
    scan3_k<<<NB, 1024>>>(off, bsum);
    cur_k<<<(NN + T - 1) / T, T>>>(off, cur, srcA);
    scatter_k<<<(NE + T - 1) / T, T>>>(ei, cur, srcA);

    // ---- layer 1 (F=128) ----
    gemm2_k<FHID><<<(NN + 127) / 128, T>>>(x, W1, h1, NN);
    alpha_k<FHID><<<(NN * 32 + T - 1) / T, T>>>(h1, a1s, a1d, as, ad);
    aggregate_k<FHID, true><<<(NN * 32 + T - 1) / T, T>>>(h1, as, ad, off, srcA, b1, acc1);

    // ---- layer 2 (F=64) ----
    gemm2_k<FOUT><<<(NN + 127) / 128, T>>>(acc1, W2, h2, NN);
    alpha_k<FOUT><<<(NN * 32 + T - 1) / T, T>>>(h2, a2s, a2d, as, ad);
    aggregate_k<FOUT, false><<<(NN * 32 + T - 1) / T, T>>>(h2, as, ad, off, srcA, b2, out);
}